// round 13
// baseline (speedup 1.0000x reference)
#include <cuda_runtime.h>
#include <cuda_bf16.h>
#include <stdint.h>

#define N_SP 4096
#define CDIM 64
#define MIDD 8
#define BDIM 4
#define NB 64             // n rows per CTA
#define MB 64             // m per tile
#define NSTEP 16          // 16 steps x 4 tiles = 64 m-tiles
#define LOG2E 1.4426950408889634f

// ---- attn dynamic smem layout (bytes) ----
#define QS_OFF 0                      // 64 rows x 16B
#define KB_OFF 1024                   // 8 bufs x 64 x 16B = 8192
#define VB_OFF 9216                   // 8 bufs x 9216
#define VSTRB 144
#define VBUF (64 * VSTRB)             // 9216
#define SMEM_DYN (VB_OFF + 8 * VBUF)  // 82944
// epilogue overlays (loop buffers dead): 4 planes of [64c][68n] f32
#define OSTR 68
#define PLANE (CDIM * OSTR * 4)       // 17408
#define EP_OS 0
#define EP_DSM (4 * PLANE)            // 69632, 256 floats
#define EP_RS (EP_DSM + 1024)         // 70656, 64 floats

typedef unsigned long long ull;

// bf16 scratch (allocation-free rule: __device__ globals)
__device__ __nv_bfloat16 g_qb[BDIM * N_SP * MIDD];   // [b][n][8c], pre-scaled by log2e
__device__ __nv_bfloat16 g_kb[BDIM * N_SP * MIDD];   // [b][m][8c]
__device__ __nv_bfloat16 g_vb[BDIM * CDIM * N_SP];   // [b][c][m]

__device__ __forceinline__ uint32_t smem_u32(const void* p) {
    uint32_t a;
    asm("{ .reg .u64 t; cvta.to.shared.u64 t, %1; cvt.u32.u64 %0, t; }"
        : "=r"(a) : "l"(p));
    return a;
}
__device__ __forceinline__ void ldsm_x4(uint32_t& r0, uint32_t& r1,
                                        uint32_t& r2, uint32_t& r3, uint32_t a) {
    asm volatile("ldmatrix.sync.aligned.m8n8.x4.shared.b16 {%0,%1,%2,%3}, [%4];"
                 : "=r"(r0), "=r"(r1), "=r"(r2), "=r"(r3) : "r"(a));
}
__device__ __forceinline__ void mma_16808(float* d, uint32_t a0, uint32_t a1,
                                          uint32_t b0) {
    asm volatile(
        "mma.sync.aligned.m16n8k8.row.col.f32.bf16.bf16.f32 "
        "{%0,%1,%2,%3}, {%4,%5}, {%6}, {%7,%7,%7,%7};"
        : "=f"(d[0]), "=f"(d[1]), "=f"(d[2]), "=f"(d[3])
        : "r"(a0), "r"(a1), "r"(b0), "f"(0.f));
}
__device__ __forceinline__ void mma_16816(float* d, const uint32_t* a,
                                          uint32_t b0, uint32_t b1) {
    asm volatile(
        "mma.sync.aligned.m16n8k16.row.col.f32.bf16.bf16.f32 "
        "{%0,%1,%2,%3}, {%4,%5,%6,%7}, {%8,%9}, {%0,%1,%2,%3};"
        : "+f"(d[0]), "+f"(d[1]), "+f"(d[2]), "+f"(d[3])
        : "r"(a[0]), "r"(a[1]), "r"(a[2]), "r"(a[3]), "r"(b0), "r"(b1));
}
__device__ __forceinline__ uint32_t pack_bf(float even, float odd) {
    uint32_t r;   // lo = even (first col), hi = odd
    asm("cvt.rn.bf16x2.f32 %0, %1, %2;" : "=r"(r) : "f"(odd), "f"(even));
    return r;
}
__device__ __forceinline__ uint32_t ex2b(uint32_t v) {
    uint32_t r;
    asm("ex2.approx.ftz.bf16x2 %0, %1;" : "=r"(r) : "r"(v));
    return r;
}
__device__ __forceinline__ __nv_bfloat162 u2b(uint32_t u) {
    return *reinterpret_cast<__nv_bfloat162*>(&u);
}
__device__ __forceinline__ ull f2fma(ull a, ull b, ull c) {
    ull d;
    asm("fma.rn.f32x2 %0, %1, %2, %3;" : "=l"(d) : "l"(a), "l"(b), "l"(c));
    return d;
}
__device__ __forceinline__ ull pk2(float x, float y) {
    ull r;
    asm("mov.b64 %0, {%1, %2};" : "=l"(r) : "f"(x), "f"(y));
    return r;
}
__device__ __forceinline__ float2 upk2(ull v) {
    float2 r;
    asm("mov.b64 {%0, %1}, %2;" : "=f"(r.x), "=f"(r.y) : "l"(v));
    return r;
}
__device__ __forceinline__ void cpasync16(uint32_t dst, const void* src) {
    asm volatile("cp.async.ca.shared.global [%0], [%1], 16;" :: "r"(dst), "l"(src));
}
#define CP_COMMIT() asm volatile("cp.async.commit_group;" ::: "memory")

// ---------------------------------------------------------------------------
// Kernel 1: 1x1-conv projections, 5-role split (measured ~7.5us).
// ---------------------------------------------------------------------------
__global__ __launch_bounds__(128) void qkv_kernel(
    const float* __restrict__ x,
    const float* __restrict__ Wq, const float* __restrict__ bq,
    const float* __restrict__ Wk, const float* __restrict__ bk,
    const float* __restrict__ Wv, const float* __restrict__ bv)
{
    __shared__ __align__(16) float sW[16 * CDIM];
    __shared__ float sbias[16];

    int tid = threadIdx.x;
    int role = blockIdx.x % 5;
    int p = (blockIdx.x / 5) * 128 + tid;
    int b = p >> 12;
    int n = p & (N_SP - 1);

    if (role == 0) {
        for (int i = tid; i < MIDD * CDIM; i += 128) {
            sW[i] = Wq[i] * LOG2E;
            sW[MIDD * CDIM + i] = Wk[i];
        }
        if (tid < MIDD) { sbias[tid] = bq[tid] * LOG2E; sbias[MIDD + tid] = bk[tid]; }
    } else {
        int off = (role - 1) * 16 * CDIM;
        for (int i = tid; i < 16 * CDIM; i += 128) sW[i] = Wv[off + i];
        if (tid < 16) sbias[tid] = bv[(role - 1) * 16 + tid];
    }
    __syncthreads();

    ull acc[16];
#pragma unroll
    for (int o = 0; o < 16; o++) acc[o] = 0ULL;

    const float* xp = x + (size_t)(b * CDIM) * N_SP + n;
#pragma unroll
    for (int chunk = 0; chunk < 2; chunk++) {
        ull xd[16];
#pragma unroll
        for (int j = 0; j < 16; j++) {
            float a = xp[(chunk * 32 + 2 * j) * N_SP];
            float bb = xp[(chunk * 32 + 2 * j + 1) * N_SP];
            xd[j] = pk2(a, bb);
        }
#pragma unroll
        for (int o = 0; o < 16; o++) {
            const ulonglong2* wp =
                reinterpret_cast<const ulonglong2*>(&sW[o * CDIM + chunk * 32]);
            ull a = acc[o];
#pragma unroll
            for (int i = 0; i < 8; i++) {
                ulonglong2 w = wp[i];
                a = f2fma(w.x, xd[2 * i], a);
                a = f2fma(w.y, xd[2 * i + 1], a);
            }
            acc[o] = a;
        }
    }

    float res[16];
#pragma unroll
    for (int o = 0; o < 16; o++) {
        float2 u = upk2(acc[o]);
        res[o] = u.x + u.y + sbias[o];
    }

    if (role == 0) {
        uint4 u;
        __nv_bfloat162 t0 = __floats2bfloat162_rn(res[0], res[1]);
        __nv_bfloat162 t1 = __floats2bfloat162_rn(res[2], res[3]);
        __nv_bfloat162 t2 = __floats2bfloat162_rn(res[4], res[5]);
        __nv_bfloat162 t3 = __floats2bfloat162_rn(res[6], res[7]);
        u.x = *(uint32_t*)&t0; u.y = *(uint32_t*)&t1;
        u.z = *(uint32_t*)&t2; u.w = *(uint32_t*)&t3;
        *(uint4*)(g_qb + (size_t)(b * N_SP + n) * MIDD) = u;
        t0 = __floats2bfloat162_rn(res[8], res[9]);
        t1 = __floats2bfloat162_rn(res[10], res[11]);
        t2 = __floats2bfloat162_rn(res[12], res[13]);
        t3 = __floats2bfloat162_rn(res[14], res[15]);
        u.x = *(uint32_t*)&t0; u.y = *(uint32_t*)&t1;
        u.z = *(uint32_t*)&t2; u.w = *(uint32_t*)&t3;
        *(uint4*)(g_kb + (size_t)(b * N_SP + n) * MIDD) = u;
    } else {
        int c0 = (role - 1) * 16;
#pragma unroll
        for (int j = 0; j < 16; j++)
            g_vb[(size_t)(b * CDIM + c0 + j) * N_SP + n] = __float2bfloat16(res[j]);
    }
}

// ---------------------------------------------------------------------------
// Kernel 2: HMMA flash attention, 256 threads = 8 warps.
// warp w = (rg = w>>2: rows rg*32..+32, mg = w&3: m-tiles step*4+mg).
// Per step the CTA streams 4 tiles (double-buffered, 8 buffers).
// Smem traffic per CTA identical to the 4-warp version; warps/SMSP doubled.
// Denominator: bf16x2 __hadd2 tree (ALU pipe), fp32 step accumulation.
// ---------------------------------------------------------------------------
__global__ __launch_bounds__(256, 2) void attn_kernel(
    const float* __restrict__ x,
    const float* __restrict__ gamma,
    float* __restrict__ out)
{
    extern __shared__ __align__(16) char smem[];
    uint32_t sb = smem_u32(smem);

    int tid = threadIdx.x;
    int w = tid >> 5;
    int t = tid & 31;
    int mg = w & 3;
    int wrow = (w >> 2) * 32;
    int b = blockIdx.x >> 6;
    int n0 = (blockIdx.x & 63) * NB;

    const __nv_bfloat16* vb0 = g_vb + (size_t)b * CDIM * N_SP;
    const __nv_bfloat16* kb0 = g_kb + (size_t)b * N_SP * MIDD;

    // ---- stage Q tile [64 rows][16B] ----
    if (tid < NB) {
        *(uint4*)(smem + QS_OFF + tid * 16) =
            *(const uint4*)(g_qb + (size_t)(b * N_SP + n0 + tid) * MIDD);
    }

    // ---- prologue: step-0's 4 tiles -> parity-0 buffers ----
    // 2304 16B-chunks: [0,2048) = V (tile, c, q8), [2048,2304) = K (tile,row)
    {
#pragma unroll
        for (int i = 0; i < 9; i++) {
            int ch = tid + 256 * i;
            if (ch < 2048) {
                int tile = ch >> 9, c = (ch >> 3) & 63, q8 = ch & 7;
                cpasync16(sb + VB_OFF + (tile * 2) * VBUF + c * VSTRB + q8 * 16,
                          vb0 + c * N_SP + tile * MB + q8 * 8);
            } else {
                int r = ch - 2048;
                int tile = r >> 6, row = r & 63;
                cpasync16(sb + KB_OFF + (tile * 2) * 1024 + row * 16,
                          kb0 + (tile * MB + row) * MIDD);
            }
        }
        CP_COMMIT();
    }
    __syncthreads();

    // Q A-frags: rows wrow..wrow+31
    uint32_t qa[4];
    ldsm_x4(qa[0], qa[1], qa[2], qa[3], sb + QS_OFF + (wrow + t) * 16);

    float o0[8][4], o1[8][4];
#pragma unroll
    for (int g2 = 0; g2 < 8; g2++)
#pragma unroll
        for (int j = 0; j < 4; j++) { o0[g2][j] = 0.f; o1[g2][j] = 0.f; }
    float d0A = 0.f, d0B = 0.f, d1A = 0.f, d1B = 0.f;

    int crow_base = ((t & 16) >> 1) + (t & 7);
    int col_base = ((t >> 3) & 1) * 8;

    for (int step = 0; step < NSTEP; step++) {
        // issue next step's 4 tiles
        if (step + 1 < NSTEP) {
            int par = (step + 1) & 1;
            int m0n = (step + 1) * 4 * MB;
#pragma unroll
            for (int i = 0; i < 9; i++) {
                int ch = tid + 256 * i;
                if (ch < 2048) {
                    int tile = ch >> 9, c = (ch >> 3) & 63, q8 = ch & 7;
                    cpasync16(sb + VB_OFF + (tile * 2 + par) * VBUF + c * VSTRB + q8 * 16,
                              vb0 + c * N_SP + m0n + tile * MB + q8 * 8);
                } else {
                    int r = ch - 2048;
                    int tile = r >> 6, row = r & 63;
                    cpasync16(sb + KB_OFF + (tile * 2 + par) * 1024 + row * 16,
                              kb0 + (m0n + tile * MB + row) * MIDD);
                }
            }
            CP_COMMIT();
            asm volatile("cp.async.wait_group 1;" ::: "memory");
        } else {
            asm volatile("cp.async.wait_group 0;" ::: "memory");
        }
        __syncthreads();

        int par = step & 1;
        uint32_t kbase = sb + KB_OFF + (mg * 2 + par) * 1024;
        uint32_t vbase = sb + VB_OFF + (mg * 2 + par) * VBUF;

        // per-step bf16x2 denominator accumulators
        __nv_bfloat162 sA0 = u2b(0u), sA1 = u2b(0u);
        __nv_bfloat162 sB0 = u2b(0u), sB1 = u2b(0u);

#pragma unroll
        for (int kh = 0; kh < 2; kh++) {
            uint32_t kb4[4];
            ldsm_x4(kb4[0], kb4[1], kb4[2], kb4[3], kbase + (kh * 32 + t) * 16);
#pragma unroll
            for (int ks2 = 0; ks2 < 2; ks2++) {
                int ks = kh * 2 + ks2;
                uint32_t p0[4], p1[4];
#pragma unroll
                for (int hf = 0; hf < 2; hf++) {
                    float d0[4], d1[4];
                    mma_16808(d0, qa[0], qa[1], kb4[ks2 * 2 + hf]);
                    mma_16808(d1, qa[2], qa[3], kb4[ks2 * 2 + hf]);
                    p0[hf * 2]     = ex2b(pack_bf(d0[0], d0[1]));
                    p0[hf * 2 + 1] = ex2b(pack_bf(d0[2], d0[3]));
                    p1[hf * 2]     = ex2b(pack_bf(d1[0], d1[1]));
                    p1[hf * 2 + 1] = ex2b(pack_bf(d1[2], d1[3]));
                }
                // denominator partials on the ALU pipe
                sA0 = __hadd2(sA0, __hadd2(u2b(p0[0]), u2b(p0[2])));
                sA1 = __hadd2(sA1, __hadd2(u2b(p0[1]), u2b(p0[3])));
                sB0 = __hadd2(sB0, __hadd2(u2b(p1[0]), u2b(p1[2])));
                sB1 = __hadd2(sB1, __hadd2(u2b(p1[1]), u2b(p1[3])));
                // PV
#pragma unroll
                for (int gp = 0; gp < 4; gp++) {
                    uint32_t r0, r1, r2, r3;
                    ldsm_x4(r0, r1, r2, r3,
                            vbase + (gp * 16 + crow_base) * VSTRB + (ks * 16 + col_base) * 2);
                    mma_16816(o0[gp * 2],     p0, r0, r1);
                    mma_16816(o0[gp * 2 + 1], p0, r2, r3);
                    mma_16816(o1[gp * 2],     p1, r0, r1);
                    mma_16816(o1[gp * 2 + 1], p1, r2, r3);
                }
            }
        }
        // fold step sums into fp32
        {
            float2 f;
            f = __bfloat1622float2(sA0); d0A += f.x + f.y;
            f = __bfloat1622float2(sA1); d0B += f.x + f.y;
            f = __bfloat1622float2(sB0); d1A += f.x + f.y;
            f = __bfloat1622float2(sB1); d1B += f.x + f.y;
        }
        __syncthreads();
    }

    // ---- quad-reduce denominators (lanes hold different m-pairs) ----
    d0A += __shfl_xor_sync(~0u, d0A, 1); d0A += __shfl_xor_sync(~0u, d0A, 2);
    d0B += __shfl_xor_sync(~0u, d0B, 1); d0B += __shfl_xor_sync(~0u, d0B, 2);
    d1A += __shfl_xor_sync(~0u, d1A, 1); d1A += __shfl_xor_sync(~0u, d1A, 2);
    d1B += __shfl_xor_sync(~0u, d1B, 1); d1B += __shfl_xor_sync(~0u, d1B, 2);

    // ---- epilogue overlays: per-mg planes, then combine ----
    float* dsm = (float*)(smem + EP_DSM);
    float* rs  = (float*)(smem + EP_RS);
    float* Pl  = (float*)(smem + EP_OS + mg * PLANE);
    int nA = wrow + (t >> 2);

    if ((t & 3) == 0) {
        dsm[mg * 64 + nA]      = d0A;
        dsm[mg * 64 + nA + 8]  = d0B;
        dsm[mg * 64 + nA + 16] = d1A;
        dsm[mg * 64 + nA + 24] = d1B;
    }
#pragma unroll
    for (int g2 = 0; g2 < 8; g2++) {
        int c0 = g2 * 8 + 2 * (t & 3);
        Pl[c0 * OSTR + nA]            = o0[g2][0];
        Pl[(c0 + 1) * OSTR + nA]      = o0[g2][1];
        Pl[c0 * OSTR + nA + 8]        = o0[g2][2];
        Pl[(c0 + 1) * OSTR + nA + 8]  = o0[g2][3];
        Pl[c0 * OSTR + nA + 16]       = o1[g2][0];
        Pl[(c0 + 1) * OSTR + nA + 16] = o1[g2][1];
        Pl[c0 * OSTR + nA + 24]       = o1[g2][2];
        Pl[(c0 + 1) * OSTR + nA + 24] = o1[g2][3];
    }
    __syncthreads();
    if (tid < NB)
        rs[tid] = gamma[0] / (dsm[tid] + dsm[64 + tid] + dsm[128 + tid] + dsm[192 + tid]);
    __syncthreads();

    // ---- combine planes + residual, coalesced write ----
    float* P0p = (float*)(smem + EP_OS);
#pragma unroll
    for (int rr = 0; rr < 4; rr++) {
        int f = tid + 256 * rr;          // float4 id: 64 c-rows x 16 per row
        int c = f >> 4, j4 = f & 15;
        int idx = c * OSTR + j4 * 4;
        float4 o = *(float4*)&P0p[idx];
        float4 o1v = *(float4*)&P0p[idx + PLANE / 4];
        float4 o2v = *(float4*)&P0p[idx + 2 * (PLANE / 4)];
        float4 o3v = *(float4*)&P0p[idx + 3 * (PLANE / 4)];
        o.x += o1v.x + o2v.x + o3v.x;
        o.y += o1v.y + o2v.y + o3v.y;
        o.z += o1v.z + o2v.z + o3v.z;
        o.w += o1v.w + o2v.w + o3v.w;
        float4 rv = *(float4*)&rs[j4 * 4];
        size_t base = (size_t)(b * CDIM + c) * N_SP + n0 + j4 * 4;
        float4 xv = *(const float4*)&x[base];
        o.x = fmaf(o.x, rv.x, xv.x);
        o.y = fmaf(o.y, rv.y, xv.y);
        o.z = fmaf(o.z, rv.z, xv.z);
        o.w = fmaf(o.w, rv.w, xv.w);
        *(float4*)&out[base] = o;
    }
}

// ---------------------------------------------------------------------------
extern "C" void kernel_launch(void* const* d_in, const int* in_sizes, int n_in,
                              void* d_out, int out_size)
{
    const float* x     = (const float*)d_in[0];
    const float* Wq    = (const float*)d_in[1];
    const float* bq    = (const float*)d_in[2];
    const float* Wk    = (const float*)d_in[3];
    const float* bk    = (const float*)d_in[4];
    const float* Wv    = (const float*)d_in[5];
    const float* bv    = (const float*)d_in[6];
    const float* gamma = (const float*)d_in[7];
    float* out = (float*)d_out;

    cudaFuncSetAttribute(attn_kernel,
                         cudaFuncAttributeMaxDynamicSharedMemorySize, SMEM_DYN);

    qkv_kernel<<<640, 128>>>(x, Wq, bq, Wk, bk, Wv, bv);
    attn_kernel<<<BDIM * (N_SP / NB), 256, SMEM_DYN>>>(x, gamma, out);
}

// round 15
// speedup vs baseline: 1.1312x; 1.1312x over previous
#include <cuda_runtime.h>
#include <cuda_bf16.h>
#include <stdint.h>

#define N_SP 4096
#define CDIM 64
#define MIDD 8
#define BDIM 4
#define NB 64             // n rows per CTA
#define MB 64             // m per tile
#define NSTEP 32          // each m-group does 32 tiles of 64
#define LOG2E 1.4426950408889634f

// ---- attn dynamic smem layout (bytes): 3 pair-buffers (triple buffer) ----
#define QS_OFF 0                      // 64 rows x 16B
#define KB_OFF 1024                   // 6 bufs (pair,mg) x 1024
#define VB_OFF 7168                   // 6 bufs x 9216
#define VSTRB 144
#define VBUF (64 * VSTRB)             // 9216
#define SMEM_DYN (VB_OFF + 6 * VBUF)  // 62464
// epilogue overlays (loop buffers dead):
#define EP_DSM 0                      // 64 floats
#define EP_RS  512                    // 64 floats
#define EP_OS  4096                   // 64c x 68 floats
#define OSTR 68

typedef unsigned long long ull;

// bf16 scratch (allocation-free rule: __device__ globals)
__device__ __nv_bfloat16 g_qb[BDIM * N_SP * MIDD];   // [b][n][8c], pre-scaled by log2e
__device__ __nv_bfloat16 g_kb[BDIM * N_SP * MIDD];   // [b][m][8c]
__device__ __nv_bfloat16 g_vb[BDIM * CDIM * N_SP];   // [b][c][m]

__device__ __forceinline__ uint32_t smem_u32(const void* p) {
    uint32_t a;
    asm("{ .reg .u64 t; cvta.to.shared.u64 t, %1; cvt.u32.u64 %0, t; }"
        : "=r"(a) : "l"(p));
    return a;
}
__device__ __forceinline__ void ldsm_x4(uint32_t& r0, uint32_t& r1,
                                        uint32_t& r2, uint32_t& r3, uint32_t a) {
    asm volatile("ldmatrix.sync.aligned.m8n8.x4.shared.b16 {%0,%1,%2,%3}, [%4];"
                 : "=r"(r0), "=r"(r1), "=r"(r2), "=r"(r3) : "r"(a));
}
__device__ __forceinline__ void mma_16808(float* d, uint32_t a0, uint32_t a1,
                                          uint32_t b0) {
    asm volatile(
        "mma.sync.aligned.m16n8k8.row.col.f32.bf16.bf16.f32 "
        "{%0,%1,%2,%3}, {%4,%5}, {%6}, {%7,%7,%7,%7};"
        : "=f"(d[0]), "=f"(d[1]), "=f"(d[2]), "=f"(d[3])
        : "r"(a0), "r"(a1), "r"(b0), "f"(0.f));
}
__device__ __forceinline__ void mma_16816(float* d, const uint32_t* a,
                                          uint32_t b0, uint32_t b1) {
    asm volatile(
        "mma.sync.aligned.m16n8k16.row.col.f32.bf16.bf16.f32 "
        "{%0,%1,%2,%3}, {%4,%5,%6,%7}, {%8,%9}, {%0,%1,%2,%3};"
        : "+f"(d[0]), "+f"(d[1]), "+f"(d[2]), "+f"(d[3])
        : "r"(a[0]), "r"(a[1]), "r"(a[2]), "r"(a[3]), "r"(b0), "r"(b1));
}
__device__ __forceinline__ uint32_t pack_bf(float even, float odd) {
    uint32_t r;   // lo = even (first col), hi = odd
    asm("cvt.rn.bf16x2.f32 %0, %1, %2;" : "=r"(r) : "f"(odd), "f"(even));
    return r;
}
__device__ __forceinline__ uint32_t ex2b(uint32_t v) {
    uint32_t r;
    asm("ex2.approx.ftz.bf16x2 %0, %1;" : "=r"(r) : "r"(v));
    return r;
}
__device__ __forceinline__ __nv_bfloat162 u2b(uint32_t u) {
    return *reinterpret_cast<__nv_bfloat162*>(&u);
}
__device__ __forceinline__ ull f2fma(ull a, ull b, ull c) {
    ull d;
    asm("fma.rn.f32x2 %0, %1, %2, %3;" : "=l"(d) : "l"(a), "l"(b), "l"(c));
    return d;
}
__device__ __forceinline__ ull pk2(float x, float y) {
    ull r;
    asm("mov.b64 %0, {%1, %2};" : "=l"(r) : "f"(x), "f"(y));
    return r;
}
__device__ __forceinline__ float2 upk2(ull v) {
    float2 r;
    asm("mov.b64 {%0, %1}, %2;" : "=f"(r.x), "=f"(r.y) : "l"(v));
    return r;
}
__device__ __forceinline__ void cpasync16(uint32_t dst, const void* src) {
    asm volatile("cp.async.ca.shared.global [%0], [%1], 16;" :: "r"(dst), "l"(src));
}
#define CP_COMMIT() asm volatile("cp.async.commit_group;" ::: "memory")

// ---------------------------------------------------------------------------
// Kernel 1: 1x1-conv projections, 5-role split (measured ~7.5us).
// ---------------------------------------------------------------------------
__global__ __launch_bounds__(128) void qkv_kernel(
    const float* __restrict__ x,
    const float* __restrict__ Wq, const float* __restrict__ bq,
    const float* __restrict__ Wk, const float* __restrict__ bk,
    const float* __restrict__ Wv, const float* __restrict__ bv)
{
    __shared__ __align__(16) float sW[16 * CDIM];
    __shared__ float sbias[16];

    int tid = threadIdx.x;
    int role = blockIdx.x % 5;
    int p = (blockIdx.x / 5) * 128 + tid;
    int b = p >> 12;
    int n = p & (N_SP - 1);

    if (role == 0) {
        for (int i = tid; i < MIDD * CDIM; i += 128) {
            sW[i] = Wq[i] * LOG2E;
            sW[MIDD * CDIM + i] = Wk[i];
        }
        if (tid < MIDD) { sbias[tid] = bq[tid] * LOG2E; sbias[MIDD + tid] = bk[tid]; }
    } else {
        int off = (role - 1) * 16 * CDIM;
        for (int i = tid; i < 16 * CDIM; i += 128) sW[i] = Wv[off + i];
        if (tid < 16) sbias[tid] = bv[(role - 1) * 16 + tid];
    }
    __syncthreads();

    ull acc[16];
#pragma unroll
    for (int o = 0; o < 16; o++) acc[o] = 0ULL;

    const float* xp = x + (size_t)(b * CDIM) * N_SP + n;
#pragma unroll
    for (int chunk = 0; chunk < 2; chunk++) {
        ull xd[16];
#pragma unroll
        for (int j = 0; j < 16; j++) {
            float a = xp[(chunk * 32 + 2 * j) * N_SP];
            float bb = xp[(chunk * 32 + 2 * j + 1) * N_SP];
            xd[j] = pk2(a, bb);
        }
#pragma unroll
        for (int o = 0; o < 16; o++) {
            const ulonglong2* wp =
                reinterpret_cast<const ulonglong2*>(&sW[o * CDIM + chunk * 32]);
            ull a = acc[o];
#pragma unroll
            for (int i = 0; i < 8; i++) {
                ulonglong2 w = wp[i];
                a = f2fma(w.x, xd[2 * i], a);
                a = f2fma(w.y, xd[2 * i + 1], a);
            }
            acc[o] = a;
        }
    }

    float res[16];
#pragma unroll
    for (int o = 0; o < 16; o++) {
        float2 u = upk2(acc[o]);
        res[o] = u.x + u.y + sbias[o];
    }

    if (role == 0) {
        uint4 u;
        __nv_bfloat162 t0 = __floats2bfloat162_rn(res[0], res[1]);
        __nv_bfloat162 t1 = __floats2bfloat162_rn(res[2], res[3]);
        __nv_bfloat162 t2 = __floats2bfloat162_rn(res[4], res[5]);
        __nv_bfloat162 t3 = __floats2bfloat162_rn(res[6], res[7]);
        u.x = *(uint32_t*)&t0; u.y = *(uint32_t*)&t1;
        u.z = *(uint32_t*)&t2; u.w = *(uint32_t*)&t3;
        *(uint4*)(g_qb + (size_t)(b * N_SP + n) * MIDD) = u;
        t0 = __floats2bfloat162_rn(res[8], res[9]);
        t1 = __floats2bfloat162_rn(res[10], res[11]);
        t2 = __floats2bfloat162_rn(res[12], res[13]);
        t3 = __floats2bfloat162_rn(res[14], res[15]);
        u.x = *(uint32_t*)&t0; u.y = *(uint32_t*)&t1;
        u.z = *(uint32_t*)&t2; u.w = *(uint32_t*)&t3;
        *(uint4*)(g_kb + (size_t)(b * N_SP + n) * MIDD) = u;
    } else {
        int c0 = (role - 1) * 16;
#pragma unroll
        for (int j = 0; j < 16; j++)
            g_vb[(size_t)(b * CDIM + c0 + j) * N_SP + n] = __float2bfloat16(res[j]);
    }
}

// ---------------------------------------------------------------------------
// Kernel 2: HMMA flash attention (R12 best shape: NB=64, MB=64, grid 256,
// 4 warps, mg=w&1, rows (w>>1)*32) with:
//   - TRIPLE-buffered tile pairs -> ONE __syncthreads per step (was 2)
//   - hadd2 ALU-pipe denominator (ones-MMA removed: tensor work -17%)
//   - ex2.approx.ftz.bf16x2 softmax (exp output = PV A-frag)
// ---------------------------------------------------------------------------
__global__ __launch_bounds__(128, 2) void attn_kernel(
    const float* __restrict__ x,
    const float* __restrict__ gamma,
    float* __restrict__ out)
{
    extern __shared__ __align__(16) char smem[];
    uint32_t sb = smem_u32(smem);

    int tid = threadIdx.x;
    int w = tid >> 5;
    int t = tid & 31;
    int mg = w & 1;
    int wrow = (w >> 1) * 32;
    int b = blockIdx.x >> 6;
    int n0 = (blockIdx.x & 63) * NB;

    const __nv_bfloat16* vb0 = g_vb + (size_t)b * CDIM * N_SP;
    const __nv_bfloat16* kb0 = g_kb + (size_t)b * N_SP * MIDD;

    // ---- stage Q tile [64 rows][16B] ----
    if (tid < NB) {
        *(uint4*)(smem + QS_OFF + tid * 16) =
            *(const uint4*)(g_qb + (size_t)(b * N_SP + n0 + tid) * MIDD);
    }

    // ---- prologue: pair 0 (tiles 0,1) -> buffer 0 ----
    {
#pragma unroll
        for (int i = 0; i < 8; i++) {
            int ch = tid + 128 * i;
            int tile = ch >> 9;
            int c2 = ch & 511;
            int c = c2 >> 3, q8 = c2 & 7;
            cpasync16(sb + VB_OFF + tile * VBUF + c * VSTRB + q8 * 16,
                      vb0 + c * N_SP + tile * MB + q8 * 8);
        }
        {
            int tile = tid >> 6, row = tid & 63;
            cpasync16(sb + KB_OFF + tile * 1024 + row * 16,
                      kb0 + (tile * MB + row) * MIDD);
        }
        CP_COMMIT();
    }
    __syncthreads();

    // Q A-frags: rows wrow..wrow+31
    uint32_t qa[4];
    ldsm_x4(qa[0], qa[1], qa[2], qa[3], sb + QS_OFF + (wrow + t) * 16);

    float o0[8][4], o1[8][4];
#pragma unroll
    for (int g2 = 0; g2 < 8; g2++)
#pragma unroll
        for (int j = 0; j < 4; j++) { o0[g2][j] = 0.f; o1[g2][j] = 0.f; }
    float d0A = 0.f, d0B = 0.f, d1A = 0.f, d1B = 0.f;

    int crow_base = ((t & 16) >> 1) + (t & 7);
    int col_base = ((t >> 3) & 1) * 8;

    int bp = 0;          // current pair buffer (0..2)
    for (int step = 0; step < NSTEP; step++) {
        // issue next pair into buffer (bp+1)%3; single barrier per step
        if (step + 1 < NSTEP) {
            int nbp = (bp == 2) ? 0 : bp + 1;
            int m0n = 2 * (step + 1) * MB;
#pragma unroll
            for (int i = 0; i < 8; i++) {
                int ch = tid + 128 * i;
                int tile = ch >> 9;
                int c2 = ch & 511;
                int c = c2 >> 3, q8 = c2 & 7;
                cpasync16(sb + VB_OFF + (nbp * 2 + tile) * VBUF + c * VSTRB + q8 * 16,
                          vb0 + c * N_SP + m0n + tile * MB + q8 * 8);
            }
            {
                int tile = tid >> 6, row = tid & 63;
                cpasync16(sb + KB_OFF + (nbp * 2 + tile) * 1024 + row * 16,
                          kb0 + (m0n + tile * MB + row) * MIDD);
            }
            CP_COMMIT();
            asm volatile("cp.async.wait_group 1;" ::: "memory");
        } else {
            asm volatile("cp.async.wait_group 0;" ::: "memory");
        }
        __syncthreads();   // the ONLY barrier per step

        uint32_t kbase = sb + KB_OFF + (bp * 2 + mg) * 1024;
        uint32_t vbase = sb + VB_OFF + (bp * 2 + mg) * VBUF;

        // per-step bf16x2 denominator accumulators
        __nv_bfloat162 sA0 = u2b(0u), sA1 = u2b(0u);
        __nv_bfloat162 sB0 = u2b(0u), sB1 = u2b(0u);

#pragma unroll
        for (int kh = 0; kh < 2; kh++) {
            uint32_t kb4[4];
            ldsm_x4(kb4[0], kb4[1], kb4[2], kb4[3], kbase + (kh * 32 + t) * 16);
#pragma unroll
            for (int ks2 = 0; ks2 < 2; ks2++) {
                int ks = kh * 2 + ks2;
                uint32_t p0[4], p1[4];
#pragma unroll
                for (int hf = 0; hf < 2; hf++) {
                    float d0[4], d1[4];
                    mma_16808(d0, qa[0], qa[1], kb4[ks2 * 2 + hf]);
                    mma_16808(d1, qa[2], qa[3], kb4[ks2 * 2 + hf]);
                    p0[hf * 2]     = ex2b(pack_bf(d0[0], d0[1]));
                    p0[hf * 2 + 1] = ex2b(pack_bf(d0[2], d0[3]));
                    p1[hf * 2]     = ex2b(pack_bf(d1[0], d1[1]));
                    p1[hf * 2 + 1] = ex2b(pack_bf(d1[2], d1[3]));
                }
                // denominator partials on the ALU pipe
                sA0 = __hadd2(sA0, __hadd2(u2b(p0[0]), u2b(p0[2])));
                sA1 = __hadd2(sA1, __hadd2(u2b(p0[1]), u2b(p0[3])));
                sB0 = __hadd2(sB0, __hadd2(u2b(p1[0]), u2b(p1[2])));
                sB1 = __hadd2(sB1, __hadd2(u2b(p1[1]), u2b(p1[3])));
                // PV
#pragma unroll
                for (int gp = 0; gp < 4; gp++) {
                    uint32_t r0, r1, r2, r3;
                    ldsm_x4(r0, r1, r2, r3,
                            vbase + (gp * 16 + crow_base) * VSTRB + (ks * 16 + col_base) * 2);
                    mma_16816(o0[gp * 2],     p0, r0, r1);
                    mma_16816(o0[gp * 2 + 1], p0, r2, r3);
                    mma_16816(o1[gp * 2],     p1, r0, r1);
                    mma_16816(o1[gp * 2 + 1], p1, r2, r3);
                }
            }
        }
        // fold step sums into fp32
        {
            float2 f;
            f = __bfloat1622float2(sA0); d0A += f.x + f.y;
            f = __bfloat1622float2(sA1); d0B += f.x + f.y;
            f = __bfloat1622float2(sB0); d1A += f.x + f.y;
            f = __bfloat1622float2(sB1); d1B += f.x + f.y;
        }
        bp = (bp == 2) ? 0 : bp + 1;
    }

    // ---- quad-reduce denominators (lanes hold different m-pairs) ----
    d0A += __shfl_xor_sync(~0u, d0A, 1); d0A += __shfl_xor_sync(~0u, d0A, 2);
    d0B += __shfl_xor_sync(~0u, d0B, 1); d0B += __shfl_xor_sync(~0u, d0B, 2);
    d1A += __shfl_xor_sync(~0u, d1A, 1); d1A += __shfl_xor_sync(~0u, d1A, 2);
    d1B += __shfl_xor_sync(~0u, d1B, 1); d1B += __shfl_xor_sync(~0u, d1B, 2);

    __syncthreads();   // all compute done before overlaying loop buffers
    float* dsm = (float*)(smem + EP_DSM);
    float* rs  = (float*)(smem + EP_RS);
    float* Os  = (float*)(smem + EP_OS);
    int r0w = wrow + (t >> 2);

    if (mg == 0) {
        if ((t & 3) == 0) {
            dsm[r0w] = d0A; dsm[r0w + 8] = d0B;
            dsm[r0w + 16] = d1A; dsm[r0w + 24] = d1B;
        }
#pragma unroll
        for (int g2 = 0; g2 < 8; g2++) {
            int c0 = g2 * 8 + 2 * (t & 3);
            int nA = wrow + (t >> 2);
            Os[c0 * OSTR + nA]            = o0[g2][0];
            Os[(c0 + 1) * OSTR + nA]      = o0[g2][1];
            Os[c0 * OSTR + nA + 8]        = o0[g2][2];
            Os[(c0 + 1) * OSTR + nA + 8]  = o0[g2][3];
            Os[c0 * OSTR + nA + 16]       = o1[g2][0];
            Os[(c0 + 1) * OSTR + nA + 16] = o1[g2][1];
            Os[c0 * OSTR + nA + 24]       = o1[g2][2];
            Os[(c0 + 1) * OSTR + nA + 24] = o1[g2][3];
        }
    }
    __syncthreads();
    if (mg == 1) {
        if ((t & 3) == 0) {
            dsm[r0w] += d0A; dsm[r0w + 8] += d0B;
            dsm[r0w + 16] += d1A; dsm[r0w + 24] += d1B;
        }
#pragma unroll
        for (int g2 = 0; g2 < 8; g2++) {
            int c0 = g2 * 8 + 2 * (t & 3);
            int nA = wrow + (t >> 2);
            Os[c0 * OSTR + nA]            += o0[g2][0];
            Os[(c0 + 1) * OSTR + nA]      += o0[g2][1];
            Os[c0 * OSTR + nA + 8]        += o0[g2][2];
            Os[(c0 + 1) * OSTR + nA + 8]  += o0[g2][3];
            Os[c0 * OSTR + nA + 16]       += o1[g2][0];
            Os[(c0 + 1) * OSTR + nA + 16] += o1[g2][1];
            Os[c0 * OSTR + nA + 24]       += o1[g2][2];
            Os[(c0 + 1) * OSTR + nA + 24] += o1[g2][3];
        }
    }
    __syncthreads();
    if (tid < NB) rs[tid] = gamma[0] / dsm[tid];
    __syncthreads();

    // ---- coalesced write: out[c][n] = Os*rs + x ----
#pragma unroll
    for (int rr = 0; rr < 8; rr++) {
        int f = tid + 128 * rr;          // float4 id: 64 c-rows x 16 per row
        int c = f >> 4, j4 = f & 15;
        float4 o = *(float4*)&Os[c * OSTR + j4 * 4];
        float4 rv = *(float4*)&rs[j4 * 4];
        size_t base = (size_t)(b * CDIM + c) * N_SP + n0 + j4 * 4;
        float4 xv = *(const float4*)&x[base];
        o.x = fmaf(o.x, rv.x, xv.x);
        o.y = fmaf(o.y, rv.y, xv.y);
        o.z = fmaf(o.z, rv.z, xv.z);
        o.w = fmaf(o.w, rv.w, xv.w);
        *(float4*)&out[base] = o;
    }
}

// ---------------------------------------------------------------------------
extern "C" void kernel_launch(void* const* d_in, const int* in_sizes, int n_in,
                              void* d_out, int out_size)
{
    const float* x     = (const float*)d_in[0];
    const float* Wq    = (const float*)d_in[1];
    const float* bq    = (const float*)d_in[2];
    const float* Wk    = (const float*)d_in[3];
    const float* bk    = (const float*)d_in[4];
    const float* Wv    = (const float*)d_in[5];
    const float* bv    = (const float*)d_in[6];
    const float* gamma = (const float*)d_in[7];
    float* out = (float*)d_out;

    cudaFuncSetAttribute(attn_kernel,
                         cudaFuncAttributeMaxDynamicSharedMemorySize, SMEM_DYN);

    qkv_kernel<<<640, 128>>>(x, Wq, bq, Wk, bk, Wv, bv);
    attn_kernel<<<BDIM * (N_SP / NB), 128, SMEM_DYN>>>(x, gamma, out);
}

// round 16
// speedup vs baseline: 1.1341x; 1.0026x over previous
#include <cuda_runtime.h>
#include <cuda_bf16.h>
#include <stdint.h>

#define N_SP 4096
#define CDIM 64
#define MIDD 8
#define BDIM 4
#define NB 64             // n rows per CTA
#define MB 64             // m per tile
#define NSTEP 32          // each m-group does 32 tiles of 64
#define LOG2E 1.4426950408889634f

// ---- attn dynamic smem layout (bytes): 3 pair-buffers (triple buffer) ----
#define QS_OFF 0                      // 64 rows x 16B
#define KB_OFF 1024                   // 6 bufs (pair,mg) x 1024
#define VB_OFF 7168                   // 6 bufs x 9216
#define VSTRB 144
#define VBUF (64 * VSTRB)             // 9216
#define SMEM_DYN (VB_OFF + 6 * VBUF)  // 62464
// epilogue overlays (loop buffers dead):
#define EP_DSM 0                      // 64 floats
#define EP_RS  512                    // 64 floats
#define EP_OS  4096                   // 64c x 68 floats
#define OSTR 68

typedef unsigned long long ull;

// bf16 scratch (allocation-free rule: __device__ globals)
__device__ __nv_bfloat16 g_qb[BDIM * N_SP * MIDD];   // [b][n][8c], pre-scaled by log2e
__device__ __nv_bfloat16 g_kb[BDIM * N_SP * MIDD];   // [b][m][8c]
__device__ __nv_bfloat16 g_vb[BDIM * CDIM * N_SP];   // [b][c][m]

__device__ __forceinline__ uint32_t smem_u32(const void* p) {
    uint32_t a;
    asm("{ .reg .u64 t; cvta.to.shared.u64 t, %1; cvt.u32.u64 %0, t; }"
        : "=r"(a) : "l"(p));
    return a;
}
__device__ __forceinline__ void ldsm_x4(uint32_t& r0, uint32_t& r1,
                                        uint32_t& r2, uint32_t& r3, uint32_t a) {
    asm volatile("ldmatrix.sync.aligned.m8n8.x4.shared.b16 {%0,%1,%2,%3}, [%4];"
                 : "=r"(r0), "=r"(r1), "=r"(r2), "=r"(r3) : "r"(a));
}
__device__ __forceinline__ void mma_16808(float* d, uint32_t a0, uint32_t a1,
                                          uint32_t b0) {
    asm volatile(
        "mma.sync.aligned.m16n8k8.row.col.f32.bf16.bf16.f32 "
        "{%0,%1,%2,%3}, {%4,%5}, {%6}, {%7,%7,%7,%7};"
        : "=f"(d[0]), "=f"(d[1]), "=f"(d[2]), "=f"(d[3])
        : "r"(a0), "r"(a1), "r"(b0), "f"(0.f));
}
__device__ __forceinline__ void mma_16816(float* d, const uint32_t* a,
                                          uint32_t b0, uint32_t b1) {
    asm volatile(
        "mma.sync.aligned.m16n8k16.row.col.f32.bf16.bf16.f32 "
        "{%0,%1,%2,%3}, {%4,%5,%6,%7}, {%8,%9}, {%0,%1,%2,%3};"
        : "+f"(d[0]), "+f"(d[1]), "+f"(d[2]), "+f"(d[3])
        : "r"(a[0]), "r"(a[1]), "r"(a[2]), "r"(a[3]), "r"(b0), "r"(b1));
}
__device__ __forceinline__ uint32_t pack_bf(float even, float odd) {
    uint32_t r;   // lo = even (first col), hi = odd
    asm("cvt.rn.bf16x2.f32 %0, %1, %2;" : "=r"(r) : "f"(odd), "f"(even));
    return r;
}
__device__ __forceinline__ uint32_t ex2b(uint32_t v) {
    uint32_t r;
    asm("ex2.approx.ftz.bf16x2 %0, %1;" : "=r"(r) : "r"(v));
    return r;
}
__device__ __forceinline__ __nv_bfloat162 u2b(uint32_t u) {
    return *reinterpret_cast<__nv_bfloat162*>(&u);
}
__device__ __forceinline__ ull f2fma(ull a, ull b, ull c) {
    ull d;
    asm("fma.rn.f32x2 %0, %1, %2, %3;" : "=l"(d) : "l"(a), "l"(b), "l"(c));
    return d;
}
__device__ __forceinline__ ull pk2(float x, float y) {
    ull r;
    asm("mov.b64 %0, {%1, %2};" : "=l"(r) : "f"(x), "f"(y));
    return r;
}
__device__ __forceinline__ float2 upk2(ull v) {
    float2 r;
    asm("mov.b64 {%0, %1}, %2;" : "=f"(r.x), "=f"(r.y) : "l"(v));
    return r;
}
__device__ __forceinline__ void cpasync16(uint32_t dst, const void* src) {
    asm volatile("cp.async.ca.shared.global [%0], [%1], 16;" :: "r"(dst), "l"(src));
}
#define CP_COMMIT() asm volatile("cp.async.commit_group;" ::: "memory")

// ---------------------------------------------------------------------------
// Kernel 1: 1x1-conv projections, 5-role split (measured ~7.5us).
// ---------------------------------------------------------------------------
__global__ __launch_bounds__(128) void qkv_kernel(
    const float* __restrict__ x,
    const float* __restrict__ Wq, const float* __restrict__ bq,
    const float* __restrict__ Wk, const float* __restrict__ bk,
    const float* __restrict__ Wv, const float* __restrict__ bv)
{
    __shared__ __align__(16) float sW[16 * CDIM];
    __shared__ float sbias[16];

    int tid = threadIdx.x;
    int role = blockIdx.x % 5;
    int p = (blockIdx.x / 5) * 128 + tid;
    int b = p >> 12;
    int n = p & (N_SP - 1);

    if (role == 0) {
        for (int i = tid; i < MIDD * CDIM; i += 128) {
            sW[i] = Wq[i] * LOG2E;
            sW[MIDD * CDIM + i] = Wk[i];
        }
        if (tid < MIDD) { sbias[tid] = bq[tid] * LOG2E; sbias[MIDD + tid] = bk[tid]; }
    } else {
        int off = (role - 1) * 16 * CDIM;
        for (int i = tid; i < 16 * CDIM; i += 128) sW[i] = Wv[off + i];
        if (tid < 16) sbias[tid] = bv[(role - 1) * 16 + tid];
    }
    __syncthreads();

    ull acc[16];
#pragma unroll
    for (int o = 0; o < 16; o++) acc[o] = 0ULL;

    const float* xp = x + (size_t)(b * CDIM) * N_SP + n;
#pragma unroll
    for (int chunk = 0; chunk < 2; chunk++) {
        ull xd[16];
#pragma unroll
        for (int j = 0; j < 16; j++) {
            float a = xp[(chunk * 32 + 2 * j) * N_SP];
            float bb = xp[(chunk * 32 + 2 * j + 1) * N_SP];
            xd[j] = pk2(a, bb);
        }
#pragma unroll
        for (int o = 0; o < 16; o++) {
            const ulonglong2* wp =
                reinterpret_cast<const ulonglong2*>(&sW[o * CDIM + chunk * 32]);
            ull a = acc[o];
#pragma unroll
            for (int i = 0; i < 8; i++) {
                ulonglong2 w = wp[i];
                a = f2fma(w.x, xd[2 * i], a);
                a = f2fma(w.y, xd[2 * i + 1], a);
            }
            acc[o] = a;
        }
    }

    float res[16];
#pragma unroll
    for (int o = 0; o < 16; o++) {
        float2 u = upk2(acc[o]);
        res[o] = u.x + u.y + sbias[o];
    }

    if (role == 0) {
        uint4 u;
        __nv_bfloat162 t0 = __floats2bfloat162_rn(res[0], res[1]);
        __nv_bfloat162 t1 = __floats2bfloat162_rn(res[2], res[3]);
        __nv_bfloat162 t2 = __floats2bfloat162_rn(res[4], res[5]);
        __nv_bfloat162 t3 = __floats2bfloat162_rn(res[6], res[7]);
        u.x = *(uint32_t*)&t0; u.y = *(uint32_t*)&t1;
        u.z = *(uint32_t*)&t2; u.w = *(uint32_t*)&t3;
        *(uint4*)(g_qb + (size_t)(b * N_SP + n) * MIDD) = u;
        t0 = __floats2bfloat162_rn(res[8], res[9]);
        t1 = __floats2bfloat162_rn(res[10], res[11]);
        t2 = __floats2bfloat162_rn(res[12], res[13]);
        t3 = __floats2bfloat162_rn(res[14], res[15]);
        u.x = *(uint32_t*)&t0; u.y = *(uint32_t*)&t1;
        u.z = *(uint32_t*)&t2; u.w = *(uint32_t*)&t3;
        *(uint4*)(g_kb + (size_t)(b * N_SP + n) * MIDD) = u;
    } else {
        int c0 = (role - 1) * 16;
#pragma unroll
        for (int j = 0; j < 16; j++)
            g_vb[(size_t)(b * CDIM + c0 + j) * N_SP + n] = __float2bfloat16(res[j]);
    }
}

// ---------------------------------------------------------------------------
// Kernel 2: HMMA flash attention (R15 best: triple-buffer single-barrier,
// ex2b softmax, hadd2 denominator) + INSTRUCTION DIET:
//   - all 16 V-ldsm offsets + 2 K-ldsm offsets precomputed in registers
//   - cp.async gmem pointers kept in registers, bumped by constant strides
//   - cp.async smem destinations = cycled base + precomputed offset
// ---------------------------------------------------------------------------
__global__ __launch_bounds__(128, 2) void attn_kernel(
    const float* __restrict__ x,
    const float* __restrict__ gamma,
    float* __restrict__ out)
{
    extern __shared__ __align__(16) char smem[];
    uint32_t sb = smem_u32(smem);

    int tid = threadIdx.x;
    int w = tid >> 5;
    int t = tid & 31;
    int mg = w & 1;
    int wrow = (w >> 1) * 32;
    int b = blockIdx.x >> 6;
    int n0 = (blockIdx.x & 63) * NB;

    const __nv_bfloat16* vb0 = g_vb + (size_t)b * CDIM * N_SP;
    const __nv_bfloat16* kb0 = g_kb + (size_t)b * N_SP * MIDD;

    // ---- precomputed cp.async roles (registers) ----
    int voff_s[8];
    const __nv_bfloat16* vsrc[8];
#pragma unroll
    for (int i = 0; i < 8; i++) {
        int ch = tid + 128 * i;
        int tile = ch >> 9;
        int c2 = ch & 511;
        int c = c2 >> 3, q8 = c2 & 7;
        voff_s[i] = tile * VBUF + c * VSTRB + q8 * 16;
        vsrc[i] = vb0 + c * N_SP + tile * MB + q8 * 8;
    }
    int koff_s;
    const __nv_bfloat16* ksrc;
    {
        int ktile = tid >> 6, krow = tid & 63;
        koff_s = ktile * 1024 + krow * 16;
        ksrc = kb0 + (ktile * MB + krow) * MIDD;
    }

    // ---- stage Q tile [64 rows][16B] ----
    if (tid < NB) {
        *(uint4*)(smem + QS_OFF + tid * 16) =
            *(const uint4*)(g_qb + (size_t)(b * N_SP + n0 + tid) * MIDD);
    }

    // ---- prologue: pair 0 -> buffer 0 ----
    {
#pragma unroll
        for (int i = 0; i < 8; i++)
            cpasync16(sb + VB_OFF + voff_s[i], vsrc[i]);
        cpasync16(sb + KB_OFF + koff_s, ksrc);
        CP_COMMIT();
        // advance gmem pointers to pair 1
#pragma unroll
        for (int i = 0; i < 8; i++) vsrc[i] += 2 * MB;        // +128 elements
        ksrc += 2 * MB * MIDD;                                // +1024 elements
    }
    __syncthreads();

    // Q A-frags: rows wrow..wrow+31
    uint32_t qa[4];
    ldsm_x4(qa[0], qa[1], qa[2], qa[3], sb + QS_OFF + (wrow + t) * 16);

    // ---- precomputed ldsm offsets ----
    int crow_base = ((t & 16) >> 1) + (t & 7);
    int col_base = ((t >> 3) & 1) * 8;
    int voffs[16];
#pragma unroll
    for (int ks = 0; ks < 4; ks++)
#pragma unroll
        for (int gp = 0; gp < 4; gp++)
            voffs[ks * 4 + gp] =
                (gp * 16 + crow_base) * VSTRB + (ks * 16 + col_base) * 2;
    int ko0 = t * 16, ko1 = (32 + t) * 16;

    float o0[8][4], o1[8][4];
#pragma unroll
    for (int g2 = 0; g2 < 8; g2++)
#pragma unroll
        for (int j = 0; j < 4; j++) { o0[g2][j] = 0.f; o1[g2][j] = 0.f; }
    float d0A = 0.f, d0B = 0.f, d1A = 0.f, d1B = 0.f;

    int bp = 0;          // current pair buffer (0..2)
    for (int step = 0; step < NSTEP; step++) {
        // issue next pair into buffer (bp+1)%3; single barrier per step
        if (step + 1 < NSTEP) {
            int nbp = (bp == 2) ? 0 : bp + 1;
            uint32_t vdstb = sb + VB_OFF + nbp * (2 * VBUF);
            uint32_t kdstb = sb + KB_OFF + nbp * 2048;
#pragma unroll
            for (int i = 0; i < 8; i++) {
                cpasync16(vdstb + voff_s[i], vsrc[i]);
                vsrc[i] += 2 * MB;
            }
            cpasync16(kdstb + koff_s, ksrc);
            ksrc += 2 * MB * MIDD;
            CP_COMMIT();
            asm volatile("cp.async.wait_group 1;" ::: "memory");
        } else {
            asm volatile("cp.async.wait_group 0;" ::: "memory");
        }
        __syncthreads();   // the ONLY barrier per step

        uint32_t kbase = sb + KB_OFF + (bp * 2 + mg) * 1024;
        uint32_t vbase = sb + VB_OFF + (bp * 2 + mg) * VBUF;

        // per-step bf16x2 denominator accumulators
        __nv_bfloat162 sA0 = u2b(0u), sA1 = u2b(0u);
        __nv_bfloat162 sB0 = u2b(0u), sB1 = u2b(0u);

#pragma unroll
        for (int kh = 0; kh < 2; kh++) {
            uint32_t kb4[4];
            ldsm_x4(kb4[0], kb4[1], kb4[2], kb4[3],
                    kbase + (kh ? ko1 : ko0));
#pragma unroll
            for (int ks2 = 0; ks2 < 2; ks2++) {
                int ks = kh * 2 + ks2;
                uint32_t p0[4], p1[4];
#pragma unroll
                for (int hf = 0; hf < 2; hf++) {
                    float d0[4], d1[4];
                    mma_16808(d0, qa[0], qa[1], kb4[ks2 * 2 + hf]);
                    mma_16808(d1, qa[2], qa[3], kb4[ks2 * 2 + hf]);
                    p0[hf * 2]     = ex2b(pack_bf(d0[0], d0[1]));
                    p0[hf * 2 + 1] = ex2b(pack_bf(d0[2], d0[3]));
                    p1[hf * 2]     = ex2b(pack_bf(d1[0], d1[1]));
                    p1[hf * 2 + 1] = ex2b(pack_bf(d1[2], d1[3]));
                }
                // denominator partials on the ALU pipe
                sA0 = __hadd2(sA0, __hadd2(u2b(p0[0]), u2b(p0[2])));
                sA1 = __hadd2(sA1, __hadd2(u2b(p0[1]), u2b(p0[3])));
                sB0 = __hadd2(sB0, __hadd2(u2b(p1[0]), u2b(p1[2])));
                sB1 = __hadd2(sB1, __hadd2(u2b(p1[1]), u2b(p1[3])));
                // PV (addresses: base + precomputed offset)
#pragma unroll
                for (int gp = 0; gp < 4; gp++) {
                    uint32_t r0, r1, r2, r3;
                    ldsm_x4(r0, r1, r2, r3, vbase + voffs[ks * 4 + gp]);
                    mma_16816(o0[gp * 2],     p0, r0, r1);
                    mma_16816(o0[gp * 2 + 1], p0, r2, r3);
                    mma_16816(o1[gp * 2],     p1, r0, r1);
                    mma_16816(o1[gp * 2 + 1], p1, r2, r3);
                }
            }
        }
        // fold step sums into fp32
        {
            float2 f;
            f = __bfloat1622float2(sA0); d0A += f.x + f.y;
            f = __bfloat1622float2(sA1); d0B += f.x + f.y;
            f = __bfloat1622float2(sB0); d1A += f.x + f.y;
            f = __bfloat1622float2(sB1); d1B += f.x + f.y;
        }
        bp = (bp == 2) ? 0 : bp + 1;
    }

    // ---- quad-reduce denominators (lanes hold different m-pairs) ----
    d0A += __shfl_xor_sync(~0u, d0A, 1); d0A += __shfl_xor_sync(~0u, d0A, 2);
    d0B += __shfl_xor_sync(~0u, d0B, 1); d0B += __shfl_xor_sync(~0u, d0B, 2);
    d1A += __shfl_xor_sync(~0u, d1A, 1); d1A += __shfl_xor_sync(~0u, d1A, 2);
    d1B += __shfl_xor_sync(~0u, d1B, 1); d1B += __shfl_xor_sync(~0u, d1B, 2);

    __syncthreads();   // all compute done before overlaying loop buffers
    float* dsm = (float*)(smem + EP_DSM);
    float* rs  = (float*)(smem + EP_RS);
    float* Os  = (float*)(smem + EP_OS);
    int r0w = wrow + (t >> 2);

    if (mg == 0) {
        if ((t & 3) == 0) {
            dsm[r0w] = d0A; dsm[r0w + 8] = d0B;
            dsm[r0w + 16] = d1A; dsm[r0w + 24] = d1B;
        }
#pragma unroll
        for (int g2 = 0; g2 < 8; g2++) {
            int c0 = g2 * 8 + 2 * (t & 3);
            int nA = wrow + (t >> 2);
            Os[c0 * OSTR + nA]            = o0[g2][0];
            Os[(c0 + 1) * OSTR + nA]      = o0[g2][1];
            Os[c0 * OSTR + nA + 8]        = o0[g2][2];
            Os[(c0 + 1) * OSTR + nA + 8]  = o0[g2][3];
            Os[c0 * OSTR + nA + 16]       = o1[g2][0];
            Os[(c0 + 1) * OSTR + nA + 16] = o1[g2][1];
            Os[c0 * OSTR + nA + 24]       = o1[g2][2];
            Os[(c0 + 1) * OSTR + nA + 24] = o1[g2][3];
        }
    }
    __syncthreads();
    if (mg == 1) {
        if ((t & 3) == 0) {
            dsm[r0w] += d0A; dsm[r0w + 8] += d0B;
            dsm[r0w + 16] += d1A; dsm[r0w + 24] += d1B;
        }
#pragma unroll
        for (int g2 = 0; g2 < 8; g2++) {
            int c0 = g2 * 8 + 2 * (t & 3);
            int nA = wrow + (t >> 2);
            Os[c0 * OSTR + nA]            += o0[g2][0];
            Os[(c0 + 1) * OSTR + nA]      += o0[g2][1];
            Os[c0 * OSTR + nA + 8]        += o0[g2][2];
            Os[(c0 + 1) * OSTR + nA + 8]  += o0[g2][3];
            Os[c0 * OSTR + nA + 16]       += o1[g2][0];
            Os[(c0 + 1) * OSTR + nA + 16] += o1[g2][1];
            Os[c0 * OSTR + nA + 24]       += o1[g2][2];
            Os[(c0 + 1) * OSTR + nA + 24] += o1[g2][3];
        }
    }
    __syncthreads();
    if (tid < NB) rs[tid] = gamma[0] / dsm[tid];
    __syncthreads();

    // ---- coalesced write: out[c][n] = Os*rs + x ----
#pragma unroll
    for (int rr = 0; rr < 8; rr++) {
        int f = tid + 128 * rr;          // float4 id: 64 c-rows x 16 per row
        int c = f >> 4, j4 = f & 15;
        float4 o = *(float4*)&Os[c * OSTR + j4 * 4];
        float4 rv = *(float4*)&rs[j4 * 4];
        size_t base = (size_t)(b * CDIM + c) * N_SP + n0 + j4 * 4;
        float4 xv = *(const float4*)&x[base];
        o.x = fmaf(o.x, rv.x, xv.x);
        o.y = fmaf(o.y, rv.y, xv.y);
        o.z = fmaf(o.z, rv.z, xv.z);
        o.w = fmaf(o.w, rv.w, xv.w);
        *(float4*)&out[base] = o;
    }
}

// ---------------------------------------------------------------------------
extern "C" void kernel_launch(void* const* d_in, const int* in_sizes, int n_in,
                              void* d_out, int out_size)
{
    const float* x     = (const float*)d_in[0];
    const float* Wq    = (const float*)d_in[1];
    const float* bq    = (const float*)d_in[2];
    const float* Wk    = (const float*)d_in[3];
    const float* bk    = (const float*)d_in[4];
    const float* Wv    = (const float*)d_in[5];
    const float* bv    = (const float*)d_in[6];
    const float* gamma = (const float*)d_in[7];
    float* out = (float*)d_out;

    cudaFuncSetAttribute(attn_kernel,
                         cudaFuncAttributeMaxDynamicSharedMemorySize, SMEM_DYN);

    qkv_kernel<<<640, 128>>>(x, Wq, bq, Wk, bk, Wv, bv);
    attn_kernel<<<BDIM * (N_SP / NB), 128, SMEM_DYN>>>(x, gamma, out);
}